// round 2
// baseline (speedup 1.0000x reference)
#include <cuda_runtime.h>

#define NB   64
#define TT   12
#define NN   325
#define HH   64
#define EE   32
#define LHH  128
#define NOUT 12
#define XST  97      // 1 + 64 + 32
#define MOFF 65

#define ROWS 32      // rows per CTA
#define WARPS 8
#define RPW  4       // rows per warp
#define NCHUNK ((NN + ROWS - 1) / ROWS)   // 11

// ---------------- device scratch (no allocations allowed) ----------------
__device__ float g_meta[NB * EE];                 // (B,E)
__device__ float g_hidden[3 * 4 * NB * LHH];      // (mlp,g,B,LH)
__device__ float g_Wx[4 * NB * HH];               // (g,B,H)
__device__ float g_bg[4 * NB * HH];               // (g,B,H)
__device__ float g_Wh[4 * NB * HH * HH];          // (g,B,H*H) 4 MB

// ---------------- fast activations (MUFU, high accuracy) -----------------
__device__ __forceinline__ float ex2f(float x) {
    float y; asm("ex2.approx.f32 %0,%1;" : "=f"(y) : "f"(x)); return y;
}
__device__ __forceinline__ float rcpf(float x) {
    float y; asm("rcp.approx.f32 %0,%1;" : "=f"(y) : "f"(x)); return y;
}
__device__ __forceinline__ float sig_a(float z) {
    // 1/(1+exp(-z))
    return rcpf(1.0f + ex2f(-1.4426950408889634f * z));
}
__device__ __forceinline__ float tanh_a(float z) {
    // 1 - 2/(exp(2z)+1)
    return fmaf(-2.0f, rcpf(1.0f + ex2f(2.8853900817779268f * z)), 1.0f);
}

// ---------------- K1: meta = mean over T of x[:, :, 0, 65:] --------------
__global__ void k_meta(const float* __restrict__ x) {
    int b = blockIdx.x, e = threadIdx.x;
    float s = 0.f;
    #pragma unroll
    for (int t = 0; t < TT; t++)
        s += x[((size_t)(b * TT + t) * NN + 0) * XST + MOFF + e];
    g_meta[b * EE + e] = s * (1.0f / TT);
}

// ---------------- K2: hidden = relu(meta @ W1 + b1) for 3 MLPs x 4 gates --
__global__ void k_hidden(const float* __restrict__ xW1, const float* __restrict__ xb1,
                         const float* __restrict__ hW1, const float* __restrict__ hb1,
                         const float* __restrict__ bW1, const float* __restrict__ bb1) {
    int b = blockIdx.x, g = blockIdx.y, m = blockIdx.z;
    int l = threadIdx.x;  // 0..127
    const float* W1 = (m == 0) ? xW1 : (m == 1) ? hW1 : bW1;
    const float* b1 = (m == 0) ? xb1 : (m == 1) ? hb1 : bb1;
    float acc = b1[g * LHH + l];
    #pragma unroll 8
    for (int e = 0; e < EE; e++)
        acc = fmaf(g_meta[b * EE + e], W1[(g * EE + e) * LHH + l], acc);
    g_hidden[((m * 4 + g) * NB + b) * LHH + l] = fmaxf(acc, 0.f);
}

// ---------------- K3ab: Wx and b second layers (O=64) --------------------
__global__ void k_small2(const float* __restrict__ xW2, const float* __restrict__ xb2,
                         const float* __restrict__ bW2, const float* __restrict__ bb2) {
    int b = blockIdx.x, g = blockIdx.y, m2 = blockIdx.z;   // m2: 0=Wx, 1=bias
    int k = threadIdx.x;  // 0..63
    int m = (m2 == 0) ? 0 : 2;
    const float* W2 = (m2 == 0) ? xW2 : bW2;
    const float* b2 = (m2 == 0) ? xb2 : bb2;
    const float* hid = &g_hidden[((m * 4 + g) * NB + b) * LHH];
    float acc = b2[g * HH + k];
    #pragma unroll 8
    for (int l = 0; l < LHH; l++)
        acc = fmaf(hid[l], W2[(g * LHH + l) * HH + k], acc);
    float* dst = (m2 == 0) ? g_Wx : g_bg;
    dst[(g * NB + b) * HH + k] = acc;
}

// ---------------- K3c: Wh second layer GEMM (128 -> 4096, 64 batches) ----
__global__ void k_wh2(const float* __restrict__ hW2, const float* __restrict__ hb2) {
    __shared__ float hs[16][LHH];   // 16 batches x 128
    int kchunk = blockIdx.x, btile = blockIdx.y, g = blockIdx.z;
    int tid = threadIdx.x;          // 256
    int k = kchunk * 256 + tid;
    for (int i = tid; i < 16 * LHH; i += 256) {
        int bb = i / LHH, l = i % LHH;
        hs[bb][l] = g_hidden[((1 * 4 + g) * NB + (btile * 16 + bb)) * LHH + l];
    }
    __syncthreads();
    float acc[16];
    #pragma unroll
    for (int bb = 0; bb < 16; bb++) acc[bb] = 0.f;
    #pragma unroll 4
    for (int l = 0; l < LHH; l++) {
        float w = hW2[(g * LHH + l) * 4096 + k];
        #pragma unroll
        for (int bb = 0; bb < 16; bb++) acc[bb] = fmaf(hs[bb][l], w, acc[bb]);
    }
    float bias = hb2[g * 4096 + k];
    #pragma unroll
    for (int bb = 0; bb < 16; bb++)
        g_Wh[(g * NB + (btile * 16 + bb)) * 4096 + k] = acc[bb] + bias;
}

// ---------------- K4: fused LSTM recurrence + FC head --------------------
// dynamic smem layout (float offsets)
#define OFF_WH   0                      // 4*4096 = 16384
#define OFF_WX   16384                  // 256
#define OFF_BG   16640                  // 256
#define OFF_H    16896                  // ROWS*64 = 2048
#define OFF_XS   18944                  // ROWS*12 = 384
#define OFF_FC1  19328                  // 64*32 = 2048
#define OFF_FC2  21376                  // 32*12 = 384
#define OFF_F1B  21760                  // 32
#define OFF_F2B  21792                  // 16 (pad)
#define OFF_MID  21808                  // 8*32 = 256
#define SMEM_FLOATS 22064
#define SMEM_BYTES (SMEM_FLOATS * 4)

__global__ __launch_bounds__(256, 2)
void k_lstm(const float* __restrict__ x,
            const float* __restrict__ fc1W, const float* __restrict__ fc1b,
            const float* __restrict__ fc2W, const float* __restrict__ fc2b,
            float* __restrict__ out) {
    extern __shared__ float sm[];
    float* whs  = sm + OFF_WH;
    float* wxs  = sm + OFF_WX;
    float* bgs  = sm + OFF_BG;
    float* hs   = sm + OFF_H;
    float* xss  = sm + OFF_XS;
    float* fc1s = sm + OFF_FC1;
    float* fc2s = sm + OFF_FC2;
    float* f1bs = sm + OFF_F1B;
    float* f2bs = sm + OFF_F2B;
    float* mids = sm + OFF_MID;

    int chunk = blockIdx.x, b = blockIdx.y;
    int tid = threadIdx.x;
    int n0 = chunk * ROWS;

    // ---- stage weights & inputs into SMEM ----
    #pragma unroll
    for (int g = 0; g < 4; g++) {
        const float4* src = (const float4*)&g_Wh[(g * NB + b) * 4096];
        float4* dst = (float4*)&whs[g * 4096];
        for (int i = tid; i < 1024; i += 256) dst[i] = src[i];
    }
    {
        int g = tid / 64, k = tid % 64;   // 256 threads exactly
        wxs[tid] = g_Wx[(g * NB + b) * HH + k];
        bgs[tid] = g_bg[(g * NB + b) * HH + k];
    }
    for (int i = tid; i < ROWS * HH; i += 256) hs[i] = 0.f;
    for (int i = tid; i < ROWS * TT; i += 256) {
        int r = i / TT, t = i % TT;
        int n = n0 + r;
        xss[r * TT + t] = (n < NN) ? x[((size_t)(b * TT + t) * NN + n) * XST] : 0.f;
    }
    for (int i = tid; i < HH * 32; i += 256) fc1s[i] = fc1W[i];
    for (int i = tid; i < 32 * NOUT; i += 256) fc2s[i] = fc2W[i];
    if (tid < 32) f1bs[tid] = fc1b[tid];
    if (tid < NOUT) f2bs[tid] = fc2b[tid];
    __syncthreads();

    int w = tid / 32, l = tid % 32;
    int k0 = 2 * l;

    // per-lane gate params (reused 12x)
    float wx[4][2], bl[4][2];
    #pragma unroll
    for (int g = 0; g < 4; g++) {
        wx[g][0] = wxs[g * HH + k0];     wx[g][1] = wxs[g * HH + k0 + 1];
        bl[g][0] = bgs[g * HH + k0];     bl[g][1] = bgs[g * HH + k0 + 1];
    }

    float cst[RPW][2];
    #pragma unroll
    for (int r = 0; r < RPW; r++) { cst[r][0] = 0.f; cst[r][1] = 0.f; }

    const int row0 = w * RPW;

    for (int t = 0; t < TT; t++) {
        float acc[RPW][4][2];
        #pragma unroll
        for (int r = 0; r < RPW; r++) {
            float xv = xss[(row0 + r) * TT + t];
            #pragma unroll
            for (int g = 0; g < 4; g++) {
                acc[r][g][0] = fmaf(xv, wx[g][0], bl[g][0]);
                acc[r][g][1] = fmaf(xv, wx[g][1], bl[g][1]);
            }
        }
        // h @ Wh : lane accumulates k-pair for all 4 gates, 4 rows
        #pragma unroll 2
        for (int j4 = 0; j4 < HH; j4 += 4) {
            float4 h4[RPW];
            #pragma unroll
            for (int r = 0; r < RPW; r++)
                h4[r] = *(const float4*)&hs[(row0 + r) * HH + j4];
            #pragma unroll
            for (int jj = 0; jj < 4; jj++) {
                float2 wv[4];
                #pragma unroll
                for (int g = 0; g < 4; g++)
                    wv[g] = *(const float2*)&whs[(g * HH + j4 + jj) * HH + k0];
                #pragma unroll
                for (int r = 0; r < RPW; r++) {
                    float hj = (jj == 0) ? h4[r].x : (jj == 1) ? h4[r].y
                             : (jj == 2) ? h4[r].z : h4[r].w;
                    #pragma unroll
                    for (int g = 0; g < 4; g++) {
                        acc[r][g][0] = fmaf(hj, wv[g].x, acc[r][g][0]);
                        acc[r][g][1] = fmaf(hj, wv[g].y, acc[r][g][1]);
                    }
                }
            }
        }
        // gates + state update (c lives in registers)
        float hnew[RPW][2];
        #pragma unroll
        for (int r = 0; r < RPW; r++) {
            #pragma unroll
            for (int kk = 0; kk < 2; kk++) {
                float gv = tanh_a(acc[r][0][kk]);
                float iv = sig_a(acc[r][1][kk]);
                float fv = sig_a(acc[r][2][kk]);
                float ov = sig_a(acc[r][3][kk]);
                float cv = fmaf(cst[r][kk], fv, gv * iv);
                cst[r][kk] = cv;
                hnew[r][kk] = tanh_a(cv) * ov;
            }
        }
        __syncwarp();   // all lanes finished reading hs for this step
        #pragma unroll
        for (int r = 0; r < RPW; r++)
            *(float2*)&hs[(row0 + r) * HH + k0] = make_float2(hnew[r][0], hnew[r][1]);
        __syncwarp();   // writes visible before next step's reads
    }

    // ---- FC head: relu(h) -> 32 (relu) -> 12 ----
    #pragma unroll
    for (int r = 0; r < RPW; r++) {
        int row = row0 + r;
        int n = n0 + row;
        float m = f1bs[l];
        #pragma unroll 8
        for (int j = 0; j < HH; j++)
            m = fmaf(fmaxf(hs[row * HH + j], 0.f), fc1s[j * 32 + l], m);
        m = fmaxf(m, 0.f);
        mids[w * 32 + l] = m;
        __syncwarp();
        if (l < NOUT) {
            float o = f2bs[l];
            #pragma unroll
            for (int q = 0; q < 32; q++)
                o = fmaf(mids[w * 32 + q], fc2s[q * NOUT + l], o);
            if (n < NN) out[(b * NOUT + l) * NN + n] = o;
        }
        __syncwarp();
    }
}

// ---------------- launch ----------------
extern "C" void kernel_launch(void* const* d_in, const int* in_sizes, int n_in,
                              void* d_out, int out_size) {
    const float* x      = (const float*)d_in[0];
    const float* lwx_W1 = (const float*)d_in[1];
    const float* lwx_b1 = (const float*)d_in[2];
    const float* lwx_W2 = (const float*)d_in[3];
    const float* lwx_b2 = (const float*)d_in[4];
    const float* lwh_W1 = (const float*)d_in[5];
    const float* lwh_b1 = (const float*)d_in[6];
    const float* lwh_W2 = (const float*)d_in[7];
    const float* lwh_b2 = (const float*)d_in[8];
    const float* lb_W1  = (const float*)d_in[9];
    const float* lb_b1  = (const float*)d_in[10];
    const float* lb_W2  = (const float*)d_in[11];
    const float* lb_b2  = (const float*)d_in[12];
    const float* fc1_W  = (const float*)d_in[13];
    const float* fc1_b  = (const float*)d_in[14];
    const float* fc2_W  = (const float*)d_in[15];
    const float* fc2_b  = (const float*)d_in[16];
    float* out = (float*)d_out;

    cudaFuncSetAttribute(k_lstm, cudaFuncAttributeMaxDynamicSharedMemorySize, SMEM_BYTES);

    k_meta<<<NB, EE>>>(x);
    k_hidden<<<dim3(NB, 4, 3), LHH>>>(lwx_W1, lwx_b1, lwh_W1, lwh_b1, lb_W1, lb_b1);
    k_small2<<<dim3(NB, 4, 2), HH>>>(lwx_W2, lwx_b2, lb_W2, lb_b2);
    k_wh2<<<dim3(16, 4, 4), 256>>>(lwh_W2, lwh_b2);
    k_lstm<<<dim3(NCHUNK, NB), 256, SMEM_BYTES>>>(x, fc1_W, fc1_b, fc2_W, fc2_b, out);
}